// round 7
// baseline (speedup 1.0000x reference)
#include <cuda_runtime.h>
#include <cstdint>
#include <cstddef>

// Problem constants
#define BB    16
#define TT    8192
#define DD    192
#define KC    512
#define SPAN  8
#define NSEG  16384
#define NTOK  131072

// Output packing: q_out [B,T,D] f32 | total_loss [1] | idx_out [B,T] | boundaries [B,T]
#define OFF_LOSS 25165824
#define OFF_IDX  25165825
#define OFF_BND  25296897

// Fused kernel tiling: block = 64 segs, all 512 codes (4 nt-iters), 256 threads.
// B codebook image streamed in 24 stages of [32 d][128 codes] = 16 KB.
#define NSTAGE    24
#define STG_F     4096            // floats per stage
#define STG_B     16384

// Dynamic smem layout (bytes)
#define SM_A      0               // float [192][64] pooled, d-major     (49152)
#define SM_B      49152           // 2 x 16384 B-chunk double buffer     (32768)
#define SM_BP     81920           // float [64][4][8] boundary partials  (8192)
#define SM_PN     90112           // float [64][4] pnorm partials        (1024)
#define SM_PNORM  91136           // float [64]                          (256)
#define SM_BEST   91392           // float [64]                          (256)
#define SM_IDX    91648           // int   [64]                          (256)
#define SM_TOTAL  92160

// Device scratch (no allocations allowed)
__device__ float g_pBimg[NSTAGE * STG_F];   // [nt][ch][d32][code128]
__device__ float g_cbnorm[KC];
__device__ float g_elatent;
__device__ int   g_bcount;

// ---------------------------------------------------------------------------
// helpers (sm_100-base-safe PTX, proven on this harness)
// ---------------------------------------------------------------------------
__device__ __forceinline__ unsigned smaddr(const void* p) {
    return (unsigned)__cvta_generic_to_shared(p);
}
__device__ __forceinline__ void mbar_init(unsigned a, unsigned cnt) {
    asm volatile("mbarrier.init.shared.b64 [%0], %1;" :: "r"(a), "r"(cnt) : "memory");
}
__device__ __forceinline__ void mbar_expect(unsigned a, unsigned bytes) {
    asm volatile("mbarrier.arrive.expect_tx.shared.b64 _, [%0], %1;" :: "r"(a), "r"(bytes) : "memory");
}
__device__ __forceinline__ void mbar_arrive(unsigned a) {
    asm volatile("mbarrier.arrive.shared.b64 _, [%0];" :: "r"(a) : "memory");
}
__device__ __forceinline__ void mbar_wait(unsigned a, unsigned par) {
    asm volatile(
        "{\n\t.reg .pred P;\n"
        "WL%=:\n\t"
        "mbarrier.try_wait.parity.acquire.cta.shared::cta.b64 P, [%0], %1;\n\t"
        "@!P bra WL%=;\n\t}"
        :: "r"(a), "r"(par) : "memory");
}
__device__ __forceinline__ void bulk_g2s(unsigned dst, const void* src, unsigned bytes, unsigned mbar) {
    asm volatile(
        "cp.async.bulk.shared::cluster.global.mbarrier::complete_tx::bytes [%0], [%1], %2, [%3];"
        :: "r"(dst), "l"(src), "r"(bytes), "r"(mbar) : "memory");
}
__device__ __forceinline__ void ffma2(unsigned long long& a, unsigned long long x, unsigned long long y) {
    asm("fma.rn.f32x2 %0, %1, %2, %0;" : "+l"(a) : "l"(x), "l"(y));
}
__device__ __forceinline__ unsigned long long dup2(float p) {
    unsigned u = __float_as_uint(p);
    unsigned long long r;
    asm("mov.b64 %0, {%1, %1};" : "=l"(r) : "r"(u));
    return r;
}

// ---------------------------------------------------------------------------
// K0: codebook image (d-major per 128-code tile) + cbnorm + scalar resets
// ---------------------------------------------------------------------------
__global__ void __launch_bounds__(DD) k_prep(const float* __restrict__ cb) {
    int c = blockIdx.x, d = threadIdx.x;
    float v = cb[(size_t)c * DD + d];
    int nt = c >> 7;
    int idx = ((nt * 6 + (d >> 5)) * 32 + (d & 31)) * 128 + (c & 127);
    g_pBimg[idx] = v;
    if (c == 0 && d == 0) { g_elatent = 0.f; g_bcount = 0; }

    float s = v * v;
#pragma unroll
    for (int off = 16; off; off >>= 1) s += __shfl_down_sync(0xffffffffu, s, off);
    __shared__ float sh[6];
    if ((d & 31) == 0) sh[d >> 5] = s;
    __syncthreads();
    if (d == 0) {
        float t = 0.f;
#pragma unroll
        for (int k = 0; k < 6; k++) t += sh[k];
        g_cbnorm[c] = t;
    }
}

// ---------------------------------------------------------------------------
// K1 (fused): pool -> argmin (512 codes) -> scatter, one block per 64 segs.
// Single wave: 256 blocks, 2 blocks/SM.
// ---------------------------------------------------------------------------
__global__ void __launch_bounds__(256, 2) k_fused(const float* __restrict__ x,
                                                  const float* __restrict__ cb,
                                                  const float* __restrict__ w,
                                                  const float* __restrict__ bbias,
                                                  float* __restrict__ q,
                                                  float* __restrict__ idxo,
                                                  float* __restrict__ out_bnd) {
    extern __shared__ __align__(16) char sm[];
    float* sA     = (float*)(sm + SM_A);       // [192][64]
    char*  sB     = sm + SM_B;
    float* sBP    = (float*)(sm + SM_BP);      // [64][4][8]
    float* sPN    = (float*)(sm + SM_PN);      // [64][4]
    float* sPNORM = (float*)(sm + SM_PNORM);
    float* sBEST  = (float*)(sm + SM_BEST);
    int*   sIDX   = (int*)(sm + SM_IDX);
    __shared__ __align__(8) unsigned long long bar[4];  // full0 full1 empty0 empty1
    __shared__ int   sBC;
    __shared__ float sEL;

    int tid = threadIdx.x;
    int segbase = blockIdx.x * 64;

    unsigned full[2]  = { smaddr(&bar[0]), smaddr(&bar[1]) };
    unsigned empty[2] = { smaddr(&bar[2]), smaddr(&bar[3]) };

    if (tid == 0) {
        mbar_init(full[0], 1);    mbar_init(full[1], 1);
        mbar_init(empty[0], 256); mbar_init(empty[1], 256);
        sBC = 0; sEL = 0.f;
        asm volatile("fence.proxy.async.shared::cta;" ::: "memory");
    }
    __syncthreads();

    // kick off B stages 0,1 (independent of pooling -> overlaps phase A)
    if (tid == 0) {
#pragma unroll
        for (int st = 0; st < 2; st++) {
            mbar_expect(full[st], STG_B);
            bulk_g2s(smaddr(sB + st * STG_B), &g_pBimg[st * STG_F], STG_B, full[st]);
        }
    }

    // ================= Phase A: pooling + boundary =================
    {
        int s    = tid >> 2;      // 0..63 local seg
        int part = tid & 3;
        const float4* xr = (const float4*)x + (size_t)(segbase + s) * 384;
        const float4* w4p = (const float4*)w;

        float bpart[SPAN];
#pragma unroll
        for (int j = 0; j < SPAN; j++) bpart[j] = 0.f;
        float pnp = 0.f;

#pragma unroll 3
        for (int i = 0; i < 12; i++) {
            int d4 = i * 4 + part;
            float4 w4 = w4p[d4];
            float4 ps = make_float4(0.f, 0.f, 0.f, 0.f);
#pragma unroll
            for (int j = 0; j < SPAN; j++) {
                float4 v = xr[j * 48 + d4];
                ps.x += v.x; ps.y += v.y; ps.z += v.z; ps.w += v.w;
                bpart[j] += v.x * w4.x + v.y * w4.y + v.z * w4.z + v.w * w4.w;
            }
            ps.x *= 0.125f; ps.y *= 0.125f; ps.z *= 0.125f; ps.w *= 0.125f;
            int db = d4 * 4;
            sA[(db + 0) * 64 + s] = ps.x;
            sA[(db + 1) * 64 + s] = ps.y;
            sA[(db + 2) * 64 + s] = ps.z;
            sA[(db + 3) * 64 + s] = ps.w;
            pnp += ps.x * ps.x + ps.y * ps.y + ps.z * ps.z + ps.w * ps.w;
        }
#pragma unroll
        for (int j = 0; j < SPAN; j++) sBP[s * 32 + part * 8 + j] = bpart[j];
        sPN[s * 4 + part] = pnp;
    }
    __syncthreads();

    // boundary logits + bits + count; pnorm fold
    {
        float bias = __ldg(bbias);
        int cnt = 0;
#pragma unroll
        for (int k = 0; k < 2; k++) {
            int t2 = tid + k * 256;            // 0..511 = seg*8 + j
            int s2 = t2 >> 3, j2 = t2 & 7;
            float z = bias + sBP[s2 * 32 + j2] + sBP[s2 * 32 + 8 + j2]
                           + sBP[s2 * 32 + 16 + j2] + sBP[s2 * 32 + 24 + j2];
            bool hi = z > 0.f;
            out_bnd[(size_t)(segbase + s2) * 8 + j2] = hi ? 1.f : 0.f;
            cnt += hi ? 1 : 0;
        }
        unsigned bal0 = __ballot_sync(0xffffffffu, cnt & 1);
        unsigned bal1 = __ballot_sync(0xffffffffu, cnt >> 1);
        if ((tid & 31) == 0)
            atomicAdd(&sBC, __popc(bal0) + 2 * __popc(bal1));
        if (tid < 64)
            sPNORM[tid] = sPN[tid * 4] + sPN[tid * 4 + 1] + sPN[tid * 4 + 2] + sPN[tid * 4 + 3];
    }
    __syncthreads();

    // ================= Phase B: argmin over 512 codes =================
    int tx = tid & 15;    // 8 codes: tx*8..+7 within the 128-code tile
    int ty = tid >> 4;    // 4 segs:  ty*4..+3

    float best[4];
    int   bidx[4];
#pragma unroll
    for (int si = 0; si < 4; si++) { best[si] = 3.4e38f; bidx[si] = 0; }

    int st = 0;
    for (int nt = 0; nt < 4; nt++) {
        unsigned long long acc[4][4];
#pragma unroll
        for (int si = 0; si < 4; si++)
#pragma unroll
            for (int cj = 0; cj < 4; cj++) acc[si][cj] = 0ull;

        for (int ch = 0; ch < 6; ch++, st++) {
            int buf = st & 1;
            unsigned par = (st >> 1) & 1;
            mbar_wait(full[buf], par);

            const float* sAc = sA + ch * 32 * 64;
            const ulonglong2* B2 = (const ulonglong2*)(sB + buf * STG_B);

            float4 av[2];
            ulonglong2 bv[2][2];
            av[0]    = *(const float4*)(sAc + ty * 4);
            bv[0][0] = B2[tx * 2];
            bv[0][1] = B2[tx * 2 + 1];

#pragma unroll
            for (int d = 0; d < 32; d++) {
                int cur = d & 1, nxt = cur ^ 1;
                if (d + 1 < 32) {
                    av[nxt]    = *(const float4*)(sAc + (d + 1) * 64 + ty * 4);
                    bv[nxt][0] = B2[(d + 1) * 32 + tx * 2];
                    bv[nxt][1] = B2[(d + 1) * 32 + tx * 2 + 1];
                }
                unsigned long long p0 = dup2(av[cur].x);
                unsigned long long p1 = dup2(av[cur].y);
                unsigned long long p2 = dup2(av[cur].z);
                unsigned long long p3 = dup2(av[cur].w);
                ffma2(acc[0][0], p0, bv[cur][0].x); ffma2(acc[0][1], p0, bv[cur][0].y);
                ffma2(acc[0][2], p0, bv[cur][1].x); ffma2(acc[0][3], p0, bv[cur][1].y);
                ffma2(acc[1][0], p1, bv[cur][0].x); ffma2(acc[1][1], p1, bv[cur][0].y);
                ffma2(acc[1][2], p1, bv[cur][1].x); ffma2(acc[1][3], p1, bv[cur][1].y);
                ffma2(acc[2][0], p2, bv[cur][0].x); ffma2(acc[2][1], p2, bv[cur][0].y);
                ffma2(acc[2][2], p2, bv[cur][1].x); ffma2(acc[2][3], p2, bv[cur][1].y);
                ffma2(acc[3][0], p3, bv[cur][0].x); ffma2(acc[3][1], p3, bv[cur][0].y);
                ffma2(acc[3][2], p3, bv[cur][1].x); ffma2(acc[3][3], p3, bv[cur][1].y);
            }

            mbar_arrive(empty[buf]);
            if (tid == 0 && st + 2 < NSTAGE) {
                mbar_wait(empty[buf], par);
                mbar_expect(full[buf], STG_B);
                bulk_g2s(smaddr(sB + buf * STG_B), &g_pBimg[(st + 2) * STG_F], STG_B, full[buf]);
            }
        }

        // fold this nt's 8 codes per lane into the running argmin
#pragma unroll
        for (int cj = 0; cj < 4; cj++) {
            int c0 = nt * 128 + tx * 8 + cj * 2;
            float cn0 = __ldg(&g_cbnorm[c0]);
            float cn1 = __ldg(&g_cbnorm[c0 + 1]);
#pragma unroll
            for (int si = 0; si < 4; si++) {
                unsigned long long a = acc[si][cj];
                float lo = __uint_as_float((unsigned)a);
                float hi = __uint_as_float((unsigned)(a >> 32));
                float v0 = cn0 - 2.f * lo;
                float v1 = cn1 - 2.f * hi;
                if (v0 < best[si] || (v0 == best[si] && c0 < bidx[si])) { best[si] = v0; bidx[si] = c0; }
                if (v1 < best[si] || (v1 == best[si] && (c0 + 1) < bidx[si])) { best[si] = v1; bidx[si] = c0 + 1; }
            }
        }
    }

    // reduce across the 16 tx lanes (xor stays inside the 16-group)
#pragma unroll
    for (int off = 1; off < 16; off <<= 1) {
#pragma unroll
        for (int si = 0; si < 4; si++) {
            float ov = __shfl_xor_sync(0xffffffffu, best[si], off);
            int   oi = __shfl_xor_sync(0xffffffffu, bidx[si], off);
            if (ov < best[si] || (ov == best[si] && oi < bidx[si])) {
                best[si] = ov; bidx[si] = oi;
            }
        }
    }
    if (tx == 0) {
#pragma unroll
        for (int si = 0; si < 4; si++) {
            sBEST[ty * 4 + si] = best[si];
            sIDX[ty * 4 + si]  = bidx[si];
        }
    }
    __syncthreads();

    // e_latent: min d2 = pnorm + best
    if (tid < 64) {
        float v = sPNORM[tid] + sBEST[tid];
#pragma unroll
        for (int off = 16; off; off >>= 1) v += __shfl_down_sync(0xffffffffu, v, off);
        if ((tid & 31) == 0) atomicAdd(&sEL, v);
    }
    __syncthreads();
    if (tid == 0) {
        atomicAdd(&g_elatent, sEL);
        atomicAdd(&g_bcount, sBC);
    }

    // ================= Phase C: scatter q_out + idx_out =================
#pragma unroll 2
    for (int i = 0; i < 12; i++) {
        int task = tid + i * 256;            // 0..3071 = seg*48 + d4
        int s  = task / 48;
        int d4 = task - s * 48;
        int idx = sIDX[s];
        float4 c4 = __ldg((const float4*)(cb + (size_t)idx * DD) + d4);
        int db = d4 * 4;
        float px = sA[(db + 0) * 64 + s];
        float py = sA[(db + 1) * 64 + s];
        float pz = sA[(db + 2) * 64 + s];
        float pw = sA[(db + 3) * 64 + s];
        float4 o;
        o.x = px + (c4.x - px);
        o.y = py + (c4.y - py);
        o.z = pz + (c4.z - pz);
        o.w = pw + (c4.w - pw);
        float4* qp = (float4*)(q + (size_t)(segbase + s) * (SPAN * DD)) + d4;
#pragma unroll
        for (int j = 0; j < SPAN; j++) qp[j * 48] = o;
    }
    if (tid < 64) {
        float v = (float)sIDX[tid];
        float* ip = idxo + (size_t)(segbase + tid) * SPAN;
#pragma unroll
        for (int j = 0; j < SPAN; j++) ip[j] = v;
    }
}

// ---------------------------------------------------------------------------
// K2: finalize scalar loss
// ---------------------------------------------------------------------------
__global__ void k_final(float* __restrict__ loss_out) {
    float e  = g_elatent * (1.0f / ((float)NSEG * (float)DD));
    float br = (float)g_bcount * (1.0f / (float)NTOK);
    float bl = br - (1.0f / SPAN);
    loss_out[0] = 0.25f * e + 0.01f * bl * bl;
}

// ---------------------------------------------------------------------------
extern "C" void kernel_launch(void* const* d_in, const int* in_sizes, int n_in,
                              void* d_out, int out_size) {
    const float* x  = (const float*)d_in[0];
    const float* cb = (const float*)d_in[1];
    const float* w  = (const float*)d_in[2];
    const float* bb = (const float*)d_in[3];
    float* out  = (float*)d_out;
    float* q    = out;
    float* loss = out + OFF_LOSS;
    float* idxo = out + OFF_IDX;
    float* bnd  = out + OFF_BND;

    cudaFuncSetAttribute(k_fused, cudaFuncAttributeMaxDynamicSharedMemorySize, SM_TOTAL);

    k_prep<<<KC, DD>>>(cb);
    k_fused<<<NSEG / 64, 256, SM_TOTAL>>>(x, cb, w, bb, q, idxo, bnd);
    k_final<<<1, 1>>>(loss);
}

// round 8
// speedup vs baseline: 1.1610x; 1.1610x over previous
#include <cuda_runtime.h>
#include <cstdint>
#include <cstddef>

// Problem constants
#define BB    16
#define TT    8192
#define DD    192
#define KC    512
#define SPAN  8
#define NSEG  16384
#define NTOK  131072

// Output packing: q_out [B,T,D] f32 | total_loss [1] | idx_out [B,T] | boundaries [B,T]
#define OFF_LOSS 25165824
#define OFF_IDX  25165825
#define OFF_BND  25296897

// Fused tiling: block = 64 segs, 128 threads (tx:16 codes-groups, ty:8 seg-groups),
// thread tile = 8 segs x 8 codes. Codebook streamed DUPLICATED ({c,c} u64) in
// 48 stages of [16 d][128 codes] = 16 KB.
#define NSTAGE    48
#define STG_F2    2048            // float2 elements per stage (16*128)
#define STG_B     16384

// Dynamic smem layout (bytes)
#define SM_A      0               // float [192][64] pooled, d-major, seg-adjacent (49152)
#define SM_B      49152           // 2 x 16384 B double buffer                    (32768)
#define SM_BP     81920           // float [64][2][8] boundary partials           (4096)
#define SM_PN     86016           // float [64][2] pnorm partials                 (512)
#define SM_PNORM  86528           // float [64]                                   (256)
#define SM_BEST   86784           // float [64]                                   (256)
#define SM_IDX    87040           // int   [64]                                   (256)
#define SM_TOTAL  87296

// Device scratch (no allocations allowed)
__device__ float2 g_pBimg[NSTAGE * STG_F2];  // [nt*12+ch][d16][code128] dup {c,c}
__device__ float  g_cbnorm[KC];
__device__ float  g_elatent;
__device__ int    g_bcount;

// ---------------------------------------------------------------------------
// helpers (sm_100-base-safe PTX, proven on this harness)
// ---------------------------------------------------------------------------
__device__ __forceinline__ unsigned smaddr(const void* p) {
    return (unsigned)__cvta_generic_to_shared(p);
}
__device__ __forceinline__ void mbar_init(unsigned a, unsigned cnt) {
    asm volatile("mbarrier.init.shared.b64 [%0], %1;" :: "r"(a), "r"(cnt) : "memory");
}
__device__ __forceinline__ void mbar_expect(unsigned a, unsigned bytes) {
    asm volatile("mbarrier.arrive.expect_tx.shared.b64 _, [%0], %1;" :: "r"(a), "r"(bytes) : "memory");
}
__device__ __forceinline__ void mbar_arrive(unsigned a) {
    asm volatile("mbarrier.arrive.shared.b64 _, [%0];" :: "r"(a) : "memory");
}
__device__ __forceinline__ void mbar_wait(unsigned a, unsigned par) {
    asm volatile(
        "{\n\t.reg .pred P;\n"
        "WL%=:\n\t"
        "mbarrier.try_wait.parity.acquire.cta.shared::cta.b64 P, [%0], %1;\n\t"
        "@!P bra WL%=;\n\t}"
        :: "r"(a), "r"(par) : "memory");
}
__device__ __forceinline__ void bulk_g2s(unsigned dst, const void* src, unsigned bytes, unsigned mbar) {
    asm volatile(
        "cp.async.bulk.shared::cluster.global.mbarrier::complete_tx::bytes [%0], [%1], %2, [%3];"
        :: "r"(dst), "l"(src), "r"(bytes), "r"(mbar) : "memory");
}
__device__ __forceinline__ void ffma2(unsigned long long& a, unsigned long long x, unsigned long long y) {
    asm("fma.rn.f32x2 %0, %1, %2, %0;" : "+l"(a) : "l"(x), "l"(y));
}

// ---------------------------------------------------------------------------
// K0: duplicated codebook image + cbnorm + scalar resets
// ---------------------------------------------------------------------------
__global__ void __launch_bounds__(DD) k_prep(const float* __restrict__ cb) {
    int c = blockIdx.x, d = threadIdx.x;
    float v = cb[(size_t)c * DD + d];
    int nt = c >> 7;
    // stage = nt*12 + d/16 ; within stage: row d%16, u64 col = c%128
    int idx = (nt * 12 + (d >> 4)) * STG_F2 + (d & 15) * 128 + (c & 127);
    g_pBimg[idx] = make_float2(v, v);
    if (c == 0 && d == 0) { g_elatent = 0.f; g_bcount = 0; }

    float s = v * v;
#pragma unroll
    for (int off = 16; off; off >>= 1) s += __shfl_down_sync(0xffffffffu, s, off);
    __shared__ float sh[6];
    if ((d & 31) == 0) sh[d >> 5] = s;
    __syncthreads();
    if (d == 0) {
        float t = 0.f;
#pragma unroll
        for (int k = 0; k < 6; k++) t += sh[k];
        g_cbnorm[c] = t;
    }
}

// ---------------------------------------------------------------------------
// K1 (fused): pool -> argmin (512 codes) -> scatter. 256 blocks x 128 threads,
// 2 blocks/SM (single wave). Inner loop: 6 LDS.128 -> 32 FFMA2, zero movs
// (A = natural seg pairs, B = pre-duplicated codes).
// ---------------------------------------------------------------------------
__global__ void __launch_bounds__(128, 2) k_fused(const float* __restrict__ x,
                                                  const float* __restrict__ cb,
                                                  const float* __restrict__ w,
                                                  const float* __restrict__ bbias,
                                                  float* __restrict__ q,
                                                  float* __restrict__ idxo,
                                                  float* __restrict__ out_bnd) {
    extern __shared__ __align__(16) char sm[];
    float* sA     = (float*)(sm + SM_A);       // [192][64] seg-adjacent
    char*  sB     = sm + SM_B;
    float* sBP    = (float*)(sm + SM_BP);      // [64][2][8]
    float* sPN    = (float*)(sm + SM_PN);      // [64][2]
    float* sPNORM = (float*)(sm + SM_PNORM);
    float* sBEST  = (float*)(sm + SM_BEST);
    int*   sIDX   = (int*)(sm + SM_IDX);
    __shared__ __align__(8) unsigned long long bar[4];  // full0 full1 empty0 empty1
    __shared__ int   sBC;
    __shared__ float sEL;

    int tid = threadIdx.x;
    int segbase = blockIdx.x * 64;

    unsigned full[2]  = { smaddr(&bar[0]), smaddr(&bar[1]) };
    unsigned empty[2] = { smaddr(&bar[2]), smaddr(&bar[3]) };

    if (tid == 0) {
        mbar_init(full[0], 1);    mbar_init(full[1], 1);
        mbar_init(empty[0], 128); mbar_init(empty[1], 128);
        sBC = 0; sEL = 0.f;
        asm volatile("fence.proxy.async.shared::cta;" ::: "memory");
    }
    __syncthreads();

    // kick off B stages 0,1 (overlaps phase A)
    if (tid == 0) {
#pragma unroll
        for (int st = 0; st < 2; st++) {
            mbar_expect(full[st], STG_B);
            bulk_g2s(smaddr(sB + st * STG_B), &g_pBimg[st * STG_F2], STG_B, full[st]);
        }
    }

    // ================= Phase A: pooling + boundary =================
    {
        int s    = tid >> 1;      // 0..63 local seg
        int part = tid & 1;       // 2 d4-interleaved halves
        const float4* xr  = (const float4*)x + (size_t)(segbase + s) * 384;
        const float4* w4p = (const float4*)w;

        float bpart[SPAN];
#pragma unroll
        for (int j = 0; j < SPAN; j++) bpart[j] = 0.f;
        float pnp = 0.f;

#pragma unroll 4
        for (int i = 0; i < 24; i++) {
            int d4 = i * 2 + part;
            float4 w4 = w4p[d4];
            float4 ps = make_float4(0.f, 0.f, 0.f, 0.f);
#pragma unroll
            for (int j = 0; j < SPAN; j++) {
                float4 v = xr[j * 48 + d4];
                ps.x += v.x; ps.y += v.y; ps.z += v.z; ps.w += v.w;
                bpart[j] += v.x * w4.x + v.y * w4.y + v.z * w4.z + v.w * w4.w;
            }
            ps.x *= 0.125f; ps.y *= 0.125f; ps.z *= 0.125f; ps.w *= 0.125f;
            int db = d4 * 4;
            sA[(db + 0) * 64 + s] = ps.x;
            sA[(db + 1) * 64 + s] = ps.y;
            sA[(db + 2) * 64 + s] = ps.z;
            sA[(db + 3) * 64 + s] = ps.w;
            pnp += ps.x * ps.x + ps.y * ps.y + ps.z * ps.z + ps.w * ps.w;
        }
#pragma unroll
        for (int j = 0; j < SPAN; j++) sBP[s * 16 + part * 8 + j] = bpart[j];
        sPN[s * 2 + part] = pnp;
    }
    __syncthreads();

    // boundary logits + count; pnorm fold
    {
        float bias = __ldg(bbias);
        unsigned cnt = 0;
#pragma unroll
        for (int k = 0; k < 4; k++) {
            int t2 = tid + k * 128;            // 0..511 = seg*8 + j
            int s2 = t2 >> 3, j2 = t2 & 7;
            float z = bias + sBP[s2 * 16 + j2] + sBP[s2 * 16 + 8 + j2];
            bool hi = z > 0.f;
            out_bnd[(size_t)(segbase + s2) * 8 + j2] = hi ? 1.f : 0.f;
            cnt += hi ? 1u : 0u;
        }
        unsigned wsum = __reduce_add_sync(0xffffffffu, cnt);
        if ((tid & 31) == 0) atomicAdd(&sBC, (int)wsum);
        if (tid < 64) sPNORM[tid] = sPN[tid * 2] + sPN[tid * 2 + 1];
    }
    __syncthreads();

    // ================= Phase B: argmin over 512 codes =================
    int tx = tid & 15;    // codes: k*32 + tx*2 (+1), k=0..3, per nt-tile
    int ty = tid >> 4;    // segs:  ty*8 .. ty*8+7

    float best[8];
    int   bidx[8];
#pragma unroll
    for (int si = 0; si < 8; si++) { best[si] = 3.4e38f; bidx[si] = 0; }

    const ulonglong2* A2 = (const ulonglong2*)sA;   // row d: 16 ulonglong2 (64 floats)

    int st = 0;
    for (int nt = 0; nt < 4; nt++) {
        // acc[sp][k][h]: seg-pair sp (segs ty*8+2sp, +1), code k*32+tx*2+h
        unsigned long long acc[4][4][2];
#pragma unroll
        for (int sp = 0; sp < 4; sp++)
#pragma unroll
            for (int k = 0; k < 4; k++) { acc[sp][k][0] = 0ull; acc[sp][k][1] = 0ull; }

        for (int ch = 0; ch < 12; ch++, st++) {
            int buf = st & 1;
            unsigned par = (st >> 1) & 1;
            mbar_wait(full[buf], par);

            const ulonglong2* B2 = (const ulonglong2*)(sB + buf * STG_B);  // row d: 64 ull2
            int abase = ch * 16 * 16;    // ulonglong2 index of this chunk's first A row

            ulonglong2 av[2][2], bv[2][4];
            av[0][0] = A2[abase + ty * 2];
            av[0][1] = A2[abase + ty * 2 + 1];
#pragma unroll
            for (int k = 0; k < 4; k++) bv[0][k] = B2[k * 16 + tx];

#pragma unroll
            for (int d = 0; d < 16; d++) {
                int cur = d & 1, nxt = cur ^ 1;
                if (d + 1 < 16) {
                    av[nxt][0] = A2[abase + (d + 1) * 16 + ty * 2];
                    av[nxt][1] = A2[abase + (d + 1) * 16 + ty * 2 + 1];
#pragma unroll
                    for (int k = 0; k < 4; k++) bv[nxt][k] = B2[(d + 1) * 64 + k * 16 + tx];
                }
                unsigned long long a0 = av[cur][0].x;   // segs 0,1
                unsigned long long a1 = av[cur][0].y;   // segs 2,3
                unsigned long long a2 = av[cur][1].x;   // segs 4,5
                unsigned long long a3 = av[cur][1].y;   // segs 6,7
#pragma unroll
                for (int k = 0; k < 4; k++) {
                    ffma2(acc[0][k][0], a0, bv[cur][k].x); ffma2(acc[0][k][1], a0, bv[cur][k].y);
                    ffma2(acc[1][k][0], a1, bv[cur][k].x); ffma2(acc[1][k][1], a1, bv[cur][k].y);
                    ffma2(acc[2][k][0], a2, bv[cur][k].x); ffma2(acc[2][k][1], a2, bv[cur][k].y);
                    ffma2(acc[3][k][0], a3, bv[cur][k].x); ffma2(acc[3][k][1], a3, bv[cur][k].y);
                }
            }

            mbar_arrive(empty[buf]);
            if (tid == 0 && st + 2 < NSTAGE) {
                mbar_wait(empty[buf], par);
                mbar_expect(full[buf], STG_B);
                bulk_g2s(smaddr(sB + buf * STG_B), &g_pBimg[(st + 2) * STG_F2], STG_B, full[buf]);
            }
        }

        // fold: val = ||c||^2 - 2*dot ; lanes of acc u64 are SEGMENTS
#pragma unroll
        for (int k = 0; k < 4; k++) {
            int c0 = nt * 128 + k * 32 + tx * 2;
            float cn0 = __ldg(&g_cbnorm[c0]);
            float cn1 = __ldg(&g_cbnorm[c0 + 1]);
#pragma unroll
            for (int sp = 0; sp < 4; sp++) {
                unsigned long long u0 = acc[sp][k][0];
                unsigned long long u1 = acc[sp][k][1];
                float v00 = cn0 - 2.f * __uint_as_float((unsigned)u0);          // seg 2sp,   c0
                float v01 = cn0 - 2.f * __uint_as_float((unsigned)(u0 >> 32));  // seg 2sp+1, c0
                float v10 = cn1 - 2.f * __uint_as_float((unsigned)u1);          // seg 2sp,   c0+1
                float v11 = cn1 - 2.f * __uint_as_float((unsigned)(u1 >> 32));  // seg 2sp+1, c0+1
                int se = 2 * sp, so = 2 * sp + 1;
                if (v00 < best[se] || (v00 == best[se] && c0 < bidx[se])) { best[se] = v00; bidx[se] = c0; }
                if (v10 < best[se] || (v10 == best[se] && (c0 + 1) < bidx[se])) { best[se] = v10; bidx[se] = c0 + 1; }
                if (v01 < best[so] || (v01 == best[so] && c0 < bidx[so])) { best[so] = v01; bidx[so] = c0; }
                if (v11 < best[so] || (v11 == best[so] && (c0 + 1) < bidx[so])) { best[so] = v11; bidx[so] = c0 + 1; }
            }
        }
    }

    // reduce across the 16 tx lanes (xor stays inside the 16-group)
#pragma unroll
    for (int off = 1; off < 16; off <<= 1) {
#pragma unroll
        for (int si = 0; si < 8; si++) {
            float ov = __shfl_xor_sync(0xffffffffu, best[si], off);
            int   oi = __shfl_xor_sync(0xffffffffu, bidx[si], off);
            if (ov < best[si] || (ov == best[si] && oi < bidx[si])) {
                best[si] = ov; bidx[si] = oi;
            }
        }
    }
    if (tx == 0) {
#pragma unroll
        for (int si = 0; si < 8; si++) {
            sBEST[ty * 8 + si] = best[si];
            sIDX[ty * 8 + si]  = bidx[si];
        }
    }
    __syncthreads();

    // e_latent: min d2 = pnorm + best
    if (tid < 64) {
        float v = sPNORM[tid] + sBEST[tid];
#pragma unroll
        for (int off = 16; off; off >>= 1) v += __shfl_down_sync(0xffffffffu, v, off);
        if ((tid & 31) == 0) atomicAdd(&sEL, v);
    }
    __syncthreads();
    if (tid == 0) {
        atomicAdd(&g_elatent, sEL);
        atomicAdd(&g_bcount, sBC);
    }

    // ================= Phase C: scatter q_out + idx_out =================
#pragma unroll 2
    for (int i = 0; i < 24; i++) {
        int task = tid + i * 128;            // 0..3071 = seg*48 + d4
        int s  = task / 48;
        int d4 = task - s * 48;
        int idx = sIDX[s];
        float4 c4 = __ldg((const float4*)(cb + (size_t)idx * DD) + d4);
        int db = d4 * 4;
        float px = sA[(db + 0) * 64 + s];
        float py = sA[(db + 1) * 64 + s];
        float pz = sA[(db + 2) * 64 + s];
        float pw = sA[(db + 3) * 64 + s];
        float4 o;
        o.x = px + (c4.x - px);
        o.y = py + (c4.y - py);
        o.z = pz + (c4.z - pz);
        o.w = pw + (c4.w - pw);
        float4* qp = (float4*)(q + (size_t)(segbase + s) * (SPAN * DD)) + d4;
#pragma unroll
        for (int j = 0; j < SPAN; j++) qp[j * 48] = o;
    }
    if (tid < 64) {
        float v = (float)sIDX[tid];
        float* ip = idxo + (size_t)(segbase + tid) * SPAN;
#pragma unroll
        for (int j = 0; j < SPAN; j++) ip[j] = v;
    }
}

// ---------------------------------------------------------------------------
// K2: finalize scalar loss
// ---------------------------------------------------------------------------
__global__ void k_final(float* __restrict__ loss_out) {
    float e  = g_elatent * (1.0f / ((float)NSEG * (float)DD));
    float br = (float)g_bcount * (1.0f / (float)NTOK);
    float bl = br - (1.0f / SPAN);
    loss_out[0] = 0.25f * e + 0.01f * bl * bl;
}

// ---------------------------------------------------------------------------
extern "C" void kernel_launch(void* const* d_in, const int* in_sizes, int n_in,
                              void* d_out, int out_size) {
    const float* x  = (const float*)d_in[0];
    const float* cb = (const float*)d_in[1];
    const float* w  = (const float*)d_in[2];
    const float* bb = (const float*)d_in[3];
    float* out  = (float*)d_out;
    float* q    = out;
    float* loss = out + OFF_LOSS;
    float* idxo = out + OFF_IDX;
    float* bnd  = out + OFF_BND;

    cudaFuncSetAttribute(k_fused, cudaFuncAttributeMaxDynamicSharedMemorySize, SM_TOTAL);

    k_prep<<<KC, DD>>>(cb);
    k_fused<<<NSEG / 64, 128, SM_TOTAL>>>(x, cb, w, bb, q, idxo, bnd);
    k_final<<<1, 1>>>(loss);
}

// round 9
// speedup vs baseline: 2.1890x; 1.8853x over previous
#include <cuda_runtime.h>
#include <cuda_fp16.h>
#include <cstdint>
#include <cstddef>

// Problem constants
#define BB    16
#define TT    8192
#define DD    192
#define KC    512
#define SPAN  8
#define NSEG  16384
#define NTOK  131072

// Output packing: q_out [B,T,D] f32 | total_loss [1] | idx_out [B,T] | boundaries [B,T]
#define OFF_LOSS 25165824
#define OFF_IDX  25165825
#define OFF_BND  25296897

// MMA fused tiling: block = 64 segs x 512 codes, 256 threads (8 warps).
// Warp (wm = w&3, nh = w>>2): m16 tile wm, n64 half nh of each 128-code stage.
// Codebook streamed as 48 stages (4 nt x 12 k16-chunks), each stage =
// hi[128n][24h] + lo[128n][24h] = 12288 B (rows padded 16->24 halves for
// conflict-free ldmatrix).
#define NSTAGE   48
#define STG_B    12288
#define SPLIT_B  6144
#define LOSCALE  2048.0f
#define INVLO    (1.0f / 2048.0f)

// Dynamic smem layout (bytes). A rows padded 192->200 halves (400B stride).
#define SM_AH     0                      // half [64][200] hi          (25600)
#define SM_AL     25600                  // half [64][200] lo*2048     (25600)
#define SM_B      51200                  // 2 x 12288 stage buffers    (24576)
#define SM_CN     75776                  // float [512] cbnorm         (2048)
#define SM_BP     77824                  // float [64][4][8]           (8192)
#define SM_PN     86016                  // float [64][4]              (1024)
#define SM_PNORM  87040                  // float [64]                 (256)
#define SM_BEST2  87296                  // float [64][2]              (512)
#define SM_IDX2   87808                  // int   [64][2]              (512)
#define SM_BEST   88320                  // float [64]                 (256)
#define SM_IDX    88576                  // int   [64]                 (256)
#define SM_TOTAL  88832

// Device scratch (no allocations allowed)
__device__ __half g_Bimg[NSTAGE * 2 * 128 * 24];   // staged hi/lo codebook image
__device__ float  g_pooled[NSEG * DD];             // fp32 pooled for phase C
__device__ float  g_cbnorm[KC];
__device__ float  g_elatent;
__device__ int    g_bcount;

// ---------------------------------------------------------------------------
// helpers (sm_100-base-safe PTX)
// ---------------------------------------------------------------------------
__device__ __forceinline__ unsigned smaddr(const void* p) {
    return (unsigned)__cvta_generic_to_shared(p);
}
__device__ __forceinline__ void mbar_init(unsigned a, unsigned cnt) {
    asm volatile("mbarrier.init.shared.b64 [%0], %1;" :: "r"(a), "r"(cnt) : "memory");
}
__device__ __forceinline__ void mbar_expect(unsigned a, unsigned bytes) {
    asm volatile("mbarrier.arrive.expect_tx.shared.b64 _, [%0], %1;" :: "r"(a), "r"(bytes) : "memory");
}
__device__ __forceinline__ void mbar_arrive(unsigned a) {
    asm volatile("mbarrier.arrive.shared.b64 _, [%0];" :: "r"(a) : "memory");
}
__device__ __forceinline__ void mbar_wait(unsigned a, unsigned par) {
    asm volatile(
        "{\n\t.reg .pred P;\n"
        "WL%=:\n\t"
        "mbarrier.try_wait.parity.acquire.cta.shared::cta.b64 P, [%0], %1;\n\t"
        "@!P bra WL%=;\n\t}"
        :: "r"(a), "r"(par) : "memory");
}
__device__ __forceinline__ void bulk_g2s(unsigned dst, const void* src, unsigned bytes, unsigned mbar) {
    asm volatile(
        "cp.async.bulk.shared::cluster.global.mbarrier::complete_tx::bytes [%0], [%1], %2, [%3];"
        :: "r"(dst), "l"(src), "r"(bytes), "r"(mbar) : "memory");
}
__device__ __forceinline__ void ldsm4(uint32_t& r0, uint32_t& r1, uint32_t& r2, uint32_t& r3, unsigned a) {
    asm volatile("ldmatrix.sync.aligned.m8n8.x4.shared.b16 {%0,%1,%2,%3}, [%4];"
                 : "=r"(r0), "=r"(r1), "=r"(r2), "=r"(r3) : "r"(a));
}
__device__ __forceinline__ void mma16816(float* d, const uint32_t* a, uint32_t b0, uint32_t b1) {
    asm volatile(
        "mma.sync.aligned.m16n8k16.row.col.f32.f16.f16.f32 "
        "{%0,%1,%2,%3}, {%4,%5,%6,%7}, {%8,%9}, {%0,%1,%2,%3};"
        : "+f"(d[0]), "+f"(d[1]), "+f"(d[2]), "+f"(d[3])
        : "r"(a[0]), "r"(a[1]), "r"(a[2]), "r"(a[3]), "r"(b0), "r"(b1));
}

// ---------------------------------------------------------------------------
// K0: split codebook into hi/lo fp16 staged image + cbnorm + scalar resets
// ---------------------------------------------------------------------------
__global__ void __launch_bounds__(DD) k_prep(const float* __restrict__ cb) {
    int c = blockIdx.x, d = threadIdx.x;
    float v  = cb[(size_t)c * DD + d];
    __half hi = __float2half_rn(v);
    __half lo = __float2half_rn((v - __half2float(hi)) * LOSCALE);
    int st = (c >> 7) * 12 + (d >> 4);
    int base = st * (2 * 128 * 24);
    int roff = (c & 127) * 24 + (d & 15);
    g_Bimg[base + roff]            = hi;
    g_Bimg[base + 128 * 24 + roff] = lo;
    if (c == 0 && d == 0) { g_elatent = 0.f; g_bcount = 0; }

    float s = v * v;
#pragma unroll
    for (int off = 16; off; off >>= 1) s += __shfl_down_sync(0xffffffffu, s, off);
    __shared__ float sh[6];
    if ((d & 31) == 0) sh[d >> 5] = s;
    __syncthreads();
    if (d == 0) {
        float t = 0.f;
#pragma unroll
        for (int k = 0; k < 6; k++) t += sh[k];
        g_cbnorm[c] = t;
    }
}

// ---------------------------------------------------------------------------
// K1 (fused): pool -> HMMA argmin (512 codes) -> scatter. 256 blocks x 256
// threads, 2 blocks/SM, single wave.
// ---------------------------------------------------------------------------
__global__ void __launch_bounds__(256, 2) k_fused(const float* __restrict__ x,
                                                  const float* __restrict__ cb,
                                                  const float* __restrict__ w,
                                                  const float* __restrict__ bbias,
                                                  float* __restrict__ q,
                                                  float* __restrict__ idxo,
                                                  float* __restrict__ out_bnd) {
    extern __shared__ __align__(16) char sm[];
    __half* sAh    = (__half*)(sm + SM_AH);
    __half* sAl    = (__half*)(sm + SM_AL);
    char*   sB     = sm + SM_B;
    float*  sCN    = (float*)(sm + SM_CN);
    float*  sBP    = (float*)(sm + SM_BP);
    float*  sPN    = (float*)(sm + SM_PN);
    float*  sPNORM = (float*)(sm + SM_PNORM);
    float*  sBEST2 = (float*)(sm + SM_BEST2);
    int*    sIDX2  = (int*)(sm + SM_IDX2);
    float*  sBEST  = (float*)(sm + SM_BEST);
    int*    sIDX   = (int*)(sm + SM_IDX);
    __shared__ __align__(8) unsigned long long bar[4];
    __shared__ int   sBC;
    __shared__ float sEL;

    int tid = threadIdx.x;
    int segbase = blockIdx.x * 64;

    unsigned full[2]  = { smaddr(&bar[0]), smaddr(&bar[1]) };
    unsigned empty[2] = { smaddr(&bar[2]), smaddr(&bar[3]) };

    if (tid == 0) {
        mbar_init(full[0], 1);    mbar_init(full[1], 1);
        mbar_init(empty[0], 256); mbar_init(empty[1], 256);
        sBC = 0; sEL = 0.f;
        asm volatile("fence.proxy.async.shared::cta;" ::: "memory");
    }
    __syncthreads();

    // kick off B stages 0,1 (overlaps phase A)
    if (tid == 0) {
#pragma unroll
        for (int st = 0; st < 2; st++) {
            mbar_expect(full[st], STG_B);
            bulk_g2s(smaddr(sB + st * STG_B), &g_Bimg[(size_t)st * (2 * 128 * 24)], STG_B, full[st]);
        }
    }
    // cbnorm into smem
#pragma unroll
    for (int k = 0; k < 2; k++) sCN[tid + k * 256] = __ldg(&g_cbnorm[tid + k * 256]);

    // ================= Phase A: pooling + boundary + fp16 splits =================
    {
        int s    = tid >> 2;      // 0..63 local seg
        int part = tid & 3;
        const float4* xr  = (const float4*)x + (size_t)(segbase + s) * 384;
        const float4* w4p = (const float4*)w;

        float bpart[SPAN];
#pragma unroll
        for (int j = 0; j < SPAN; j++) bpart[j] = 0.f;
        float pnp = 0.f;

#pragma unroll 3
        for (int i = 0; i < 12; i++) {
            int d4 = i * 4 + part;
            float4 w4 = w4p[d4];
            float4 ps = make_float4(0.f, 0.f, 0.f, 0.f);
#pragma unroll
            for (int j = 0; j < SPAN; j++) {
                float4 v = xr[j * 48 + d4];
                ps.x += v.x; ps.y += v.y; ps.z += v.z; ps.w += v.w;
                bpart[j] += v.x * w4.x + v.y * w4.y + v.z * w4.z + v.w * w4.w;
            }
            ps.x *= 0.125f; ps.y *= 0.125f; ps.z *= 0.125f; ps.w *= 0.125f;

            // fp32 pooled to global (phase C reads it back; L2 resident)
            ((float4*)g_pooled)[(size_t)(segbase + s) * 48 + d4] = ps;

            // fp16 hi/lo splits into A smem [m][200] layout
            __half hx = __float2half_rn(ps.x), hy = __float2half_rn(ps.y);
            __half hz = __float2half_rn(ps.z), hw = __float2half_rn(ps.w);
            int hb = s * 200 + d4 * 4;
            *(__half2*)(sAh + hb)     = __halves2half2(hx, hy);
            *(__half2*)(sAh + hb + 2) = __halves2half2(hz, hw);
            *(__half2*)(sAl + hb) = __halves2half2(
                __float2half_rn((ps.x - __half2float(hx)) * LOSCALE),
                __float2half_rn((ps.y - __half2float(hy)) * LOSCALE));
            *(__half2*)(sAl + hb + 2) = __halves2half2(
                __float2half_rn((ps.z - __half2float(hz)) * LOSCALE),
                __float2half_rn((ps.w - __half2float(hw)) * LOSCALE));

            pnp += ps.x * ps.x + ps.y * ps.y + ps.z * ps.z + ps.w * ps.w;
        }
#pragma unroll
        for (int j = 0; j < SPAN; j++) sBP[s * 32 + part * 8 + j] = bpart[j];
        sPN[s * 4 + part] = pnp;
    }
    __syncthreads();

    // boundary logits + count; pnorm fold
    {
        float bias = __ldg(bbias);
        unsigned cnt = 0;
#pragma unroll
        for (int k = 0; k < 2; k++) {
            int t2 = tid + k * 256;            // 0..511 = seg*8 + j
            int s2 = t2 >> 3, j2 = t2 & 7;
            float z = bias + sBP[s2 * 32 + j2] + sBP[s2 * 32 + 8 + j2]
                           + sBP[s2 * 32 + 16 + j2] + sBP[s2 * 32 + 24 + j2];
            bool hi = z > 0.f;
            out_bnd[(size_t)(segbase + s2) * 8 + j2] = hi ? 1.f : 0.f;
            cnt += hi ? 1u : 0u;
        }
        unsigned wsum = __reduce_add_sync(0xffffffffu, cnt);
        if ((tid & 31) == 0) atomicAdd(&sBC, (int)wsum);
        if (tid < 64)
            sPNORM[tid] = sPN[tid * 4] + sPN[tid * 4 + 1] + sPN[tid * 4 + 2] + sPN[tid * 4 + 3];
    }
    __syncthreads();

    // ================= Phase B: HMMA argmin over 512 codes =================
    int wid  = tid >> 5;
    int lane = tid & 31;
    int wm   = wid & 3;        // m16 tile (segs wm*16..+15)
    int nh   = wid >> 2;       // n64 half of each 128-code stage

    // ldmatrix lane address offsets
    int a_moff = (lane & 7) + ((lane >> 3) & 1) * 8;
    int a_koff = (lane >> 4) * 8;
    unsigned aRow = (unsigned)((wm * 16 + a_moff) * 200 + a_koff);  // halves
    unsigned aHaddr = smaddr(sAh) + aRow * 2;
    unsigned aLaddr = smaddr(sAl) + aRow * 2;

    int b_noff = (lane & 7) + ((lane >> 4) << 3);
    int b_koff = ((lane >> 3) & 1) * 8;
    unsigned bOff = (unsigned)((nh * 64 + b_noff) * 48 + b_koff * 2);  // bytes within split

    int rowA = lane >> 2;          // 0..7 -> m rows wm*16+rowA, +8
    int colP = (lane & 3) * 2;     // code pair base within n8 tile

    float bestA = 3.4e38f, bestB = 3.4e38f;
    int   idxA = 0, idxB = 0;

    int st = 0;
    for (int nt = 0; nt < 4; nt++) {
        float dhi[8][4], dlo[8][4];
#pragma unroll
        for (int t = 0; t < 8; t++)
#pragma unroll
            for (int r = 0; r < 4; r++) { dhi[t][r] = 0.f; dlo[t][r] = 0.f; }

        for (int ch = 0; ch < 12; ch++, st++) {
            int buf = st & 1;
            unsigned par = (st >> 1) & 1;
            mbar_wait(full[buf], par);

            uint32_t ah[4], al[4];
            unsigned ka = (unsigned)(ch * 16) * 2;
            ldsm4(ah[0], ah[1], ah[2], ah[3], aHaddr + ka);
            ldsm4(al[0], al[1], al[2], al[3], aLaddr + ka);

            unsigned bh_base = smaddr(sB + buf * STG_B) + bOff;
            unsigned bl_base = bh_base + SPLIT_B;

#pragma unroll
            for (int t2 = 0; t2 < 4; t2++) {
                uint32_t bh0, bh1, bh2, bh3, bl0, bl1, bl2, bl3;
                ldsm4(bh0, bh1, bh2, bh3, bh_base + t2 * (16 * 48));
                ldsm4(bl0, bl1, bl2, bl3, bl_base + t2 * (16 * 48));
                int t = t2 * 2;
                mma16816(dhi[t],     ah, bh0, bh1);
                mma16816(dlo[t],     ah, bl0, bl1);
                mma16816(dlo[t],     al, bh0, bh1);
                mma16816(dhi[t + 1], ah, bh2, bh3);
                mma16816(dlo[t + 1], ah, bl2, bl3);
                mma16816(dlo[t + 1], al, bh2, bh3);
            }

            mbar_arrive(empty[buf]);
            if (tid == 0 && st + 2 < NSTAGE) {
                mbar_wait(empty[buf], par);
                mbar_expect(full[buf], STG_B);
                bulk_g2s(smaddr(sB + buf * STG_B),
                         &g_Bimg[(size_t)(st + 2) * (2 * 128 * 24)], STG_B, full[buf]);
            }
        }

        // fold: val = ||c||^2 - 2*(dhi + dlo/2048)
#pragma unroll
        for (int t = 0; t < 8; t++) {
            int c0 = nt * 128 + nh * 64 + t * 8 + colP;
            float cn0 = sCN[c0], cn1 = sCN[c0 + 1];
            float v00 = cn0 - 2.f * (dhi[t][0] + dlo[t][0] * INVLO);  // row A, c0
            float v01 = cn1 - 2.f * (dhi[t][1] + dlo[t][1] * INVLO);  // row A, c0+1
            float v10 = cn0 - 2.f * (dhi[t][2] + dlo[t][2] * INVLO);  // row B, c0
            float v11 = cn1 - 2.f * (dhi[t][3] + dlo[t][3] * INVLO);  // row B, c0+1
            if (v00 < bestA || (v00 == bestA && c0 < idxA)) { bestA = v00; idxA = c0; }
            if (v01 < bestA || (v01 == bestA && (c0 + 1) < idxA)) { bestA = v01; idxA = c0 + 1; }
            if (v10 < bestB || (v10 == bestB && c0 < idxB)) { bestB = v10; idxB = c0; }
            if (v11 < bestB || (v11 == bestB && (c0 + 1) < idxB)) { bestB = v11; idxB = c0 + 1; }
        }
    }

    // reduce across the 4 lanes sharing each row (xor 1,2 within quad)
#pragma unroll
    for (int off = 1; off < 4; off <<= 1) {
        float ov = __shfl_xor_sync(0xffffffffu, bestA, off);
        int   oi = __shfl_xor_sync(0xffffffffu, idxA, off);
        if (ov < bestA || (ov == bestA && oi < idxA)) { bestA = ov; idxA = oi; }
        ov = __shfl_xor_sync(0xffffffffu, bestB, off);
        oi = __shfl_xor_sync(0xffffffffu, idxB, off);
        if (ov < bestB || (ov == bestB && oi < idxB)) { bestB = ov; idxB = oi; }
    }
    if ((lane & 3) == 0) {
        int mA = wm * 16 + rowA;
        sBEST2[mA * 2 + nh] = bestA;  sIDX2[mA * 2 + nh] = idxA;
        sBEST2[(mA + 8) * 2 + nh] = bestB;  sIDX2[(mA + 8) * 2 + nh] = idxB;
    }
    __syncthreads();

    // combine the two n-halves per segment
    if (tid < 64) {
        float b0 = sBEST2[tid * 2],     b1 = sBEST2[tid * 2 + 1];
        int   i0 = sIDX2[tid * 2],      i1 = sIDX2[tid * 2 + 1];
        bool take1 = (b1 < b0) || (b1 == b0 && i1 < i0);
        float bb = take1 ? b1 : b0;
        int   ii = take1 ? i1 : i0;
        sBEST[tid] = bb;  sIDX[tid] = ii;
        float v = sPNORM[tid] + bb;
#pragma unroll
        for (int off = 16; off; off >>= 1) v += __shfl_down_sync(0xffffffffu, v, off);
        if ((tid & 31) == 0) atomicAdd(&sEL, v);
    }
    __syncthreads();
    if (tid == 0) {
        atomicAdd(&g_elatent, sEL);
        atomicAdd(&g_bcount, sBC);
    }

    // ================= Phase C: scatter q_out + idx_out =================
#pragma unroll 2
    for (int i = 0; i < 12; i++) {
        int task = tid + i * 256;            // 0..3071 = seg*48 + d4
        int s  = task / 48;
        int d4 = task - s * 48;
        int idx = sIDX[s];
        float4 c4 = __ldg((const float4*)(cb + (size_t)idx * DD) + d4);
        float4 p4 = ((const float4*)g_pooled)[(size_t)(segbase + s) * 48 + d4];
        float4 o;
        o.x = p4.x + (c4.x - p4.x);
        o.y = p4.y + (c4.y - p4.y);
        o.z = p4.z + (c4.z - p4.z);
        o.w = p4.w + (c4.w - p4.w);
        float4* qp = (float4*)(q + (size_t)(segbase + s) * (SPAN * DD)) + d4;
#pragma unroll
        for (int j = 0; j < SPAN; j++) qp[j * 48] = o;
    }
    if (tid < 64) {
        float v = (float)sIDX[tid];
        float* ip = idxo + (size_t)(segbase + tid) * SPAN;
#pragma unroll
        for (int j = 0; j < SPAN; j++) ip[j] = v;
    }
}

// ---------------------------------------------------------------------------
// K2: finalize scalar loss
// ---------------------------------------------------------------------------
__global__ void k_final(float* __restrict__ loss_out) {
    float e  = g_elatent * (1.0f / ((float)NSEG * (float)DD));
    float br = (float)g_bcount * (1.0f / (float)NTOK);
    float bl = br - (1.0f / SPAN);
    loss_out[0] = 0.25f * e + 0.01f * bl * bl;
}

// ---------------------------------------------------------------------------
extern "C" void kernel_launch(void* const* d_in, const int* in_sizes, int n_in,
                              void* d_out, int out_size) {
    const float* x  = (const float*)d_in[0];
    const float* cb = (const float*)d_in[1];
    const float* w  = (const float*)d_in[2];
    const float* bb = (const float*)d_in[3];
    float* out  = (float*)d_out;
    float* q    = out;
    float* loss = out + OFF_LOSS;
    float* idxo = out + OFF_IDX;
    float* bnd  = out + OFF_BND;

    cudaFuncSetAttribute(k_fused, cudaFuncAttributeMaxDynamicSharedMemorySize, SM_TOTAL);

    k_prep<<<KC, DD>>>(cb);
    k_fused<<<NSEG / 64, 256, SM_TOTAL>>>(x, cb, w, bb, q, idxo, bnd);
    k_final<<<1, 1>>>(loss);
}

// round 14
// speedup vs baseline: 2.2437x; 1.0250x over previous
#include <cuda_runtime.h>
#include <cuda_fp16.h>
#include <cstdint>
#include <cstddef>

// Problem constants
#define BB    16
#define TT    8192
#define DD    192
#define KC    512
#define SPAN  8
#define NSEG  16384
#define NTOK  131072

// Output packing: q_out [B,T,D] f32 | total_loss [1] | idx_out [B,T] | boundaries [B,T]
#define OFF_LOSS 25165824
#define OFF_IDX  25165825
#define OFF_BND  25296897

// MMA fused tiling: block = 64 segs x 512 codes, 256 threads (8 warps).
// Warp (wm = w&3, nh = w>>2): m16 tile wm, n64 half nh of each 128-code stage.
// Codebook streamed as 48 stages (4 nt x 12 k16-chunks), each stage =
// hi[128n][24h] + lo[128n][24h] = 12288 B, double-buffered.
// Buffer-recycle safety via per-stage __syncthreads (provably race-free).
#define NSTAGE   48
#define STG_B    12288
#define SPLIT_B  6144
#define LOSCALE  2048.0f
#define INVLO    (1.0f / 2048.0f)

// Dynamic smem layout (bytes). A rows padded 192->200 halves (400B stride).
#define SM_AH     0                      // half [64][200] hi          (25600)
#define SM_AL     25600                  // half [64][200] lo*2048     (25600)
#define SM_B      51200                  // 2 x 12288 stage buffers    (24576)
#define SM_CN     75776                  // float [512] cbnorm         (2048)
#define SM_BP     77824                  // float [64][4][8]           (8192)
#define SM_PN     86016                  // float [64][4]              (1024)
#define SM_PNORM  87040                  // float [64]                 (256)
#define SM_BEST2  87296                  // float [64][2]              (512)
#define SM_IDX2   87808                  // int   [64][2]              (512)
#define SM_BEST   88320                  // float [64]                 (256)
#define SM_IDX    88576                  // int   [64]                 (256)
#define SM_TOTAL  88832

// Device scratch (no allocations allowed)
__device__ __half g_Bimg[NSTAGE * 2 * 128 * 24];   // staged hi/lo codebook image
__device__ float  g_cbnorm[KC];
__device__ float  g_elatent;
__device__ int    g_bcount;

// ---------------------------------------------------------------------------
// helpers (sm_100-base-safe PTX)
// ---------------------------------------------------------------------------
__device__ __forceinline__ unsigned smaddr(const void* p) {
    return (unsigned)__cvta_generic_to_shared(p);
}
__device__ __forceinline__ void mbar_init(unsigned a, unsigned cnt) {
    asm volatile("mbarrier.init.shared.b64 [%0], %1;" :: "r"(a), "r"(cnt) : "memory");
}
__device__ __forceinline__ void mbar_expect(unsigned a, unsigned bytes) {
    asm volatile("mbarrier.arrive.expect_tx.shared.b64 _, [%0], %1;" :: "r"(a), "r"(bytes) : "memory");
}
__device__ __forceinline__ void mbar_wait(unsigned a, unsigned par) {
    asm volatile(
        "{\n\t.reg .pred P;\n"
        "WL%=:\n\t"
        "mbarrier.try_wait.parity.acquire.cta.shared::cta.b64 P, [%0], %1;\n\t"
        "@!P bra WL%=;\n\t}"
        :: "r"(a), "r"(par) : "memory");
}
__device__ __forceinline__ void bulk_g2s(unsigned dst, const void* src, unsigned bytes, unsigned mbar) {
    asm volatile(
        "cp.async.bulk.shared::cluster.global.mbarrier::complete_tx::bytes [%0], [%1], %2, [%3];"
        :: "r"(dst), "l"(src), "r"(bytes), "r"(mbar) : "memory");
}
__device__ __forceinline__ void ldsm4(uint32_t& r0, uint32_t& r1, uint32_t& r2, uint32_t& r3, unsigned a) {
    asm volatile("ldmatrix.sync.aligned.m8n8.x4.shared.b16 {%0,%1,%2,%3}, [%4];"
                 : "=r"(r0), "=r"(r1), "=r"(r2), "=r"(r3) : "r"(a));
}
__device__ __forceinline__ void mma16816(float* d, const uint32_t* a, uint32_t b0, uint32_t b1) {
    asm volatile(
        "mma.sync.aligned.m16n8k16.row.col.f32.f16.f16.f32 "
        "{%0,%1,%2,%3}, {%4,%5,%6,%7}, {%8,%9}, {%0,%1,%2,%3};"
        : "+f"(d[0]), "+f"(d[1]), "+f"(d[2]), "+f"(d[3])
        : "r"(a[0]), "r"(a[1]), "r"(a[2]), "r"(a[3]), "r"(b0), "r"(b1));
}

// ---------------------------------------------------------------------------
// K0: split codebook into hi/lo fp16 staged image + cbnorm + scalar resets.
// 128 blocks x 192 threads, 4 codes per block (MLP across the 4 loads).
// ---------------------------------------------------------------------------
__global__ void __launch_bounds__(DD) k_prep(const float* __restrict__ cb) {
    int c0 = blockIdx.x * 4, d = threadIdx.x;
    float v[4];
#pragma unroll
    for (int k = 0; k < 4; k++) v[k] = __ldg(&cb[(size_t)(c0 + k) * DD + d]);

#pragma unroll
    for (int k = 0; k < 4; k++) {
        int c = c0 + k;
        __half hi = __float2half_rn(v[k]);
        __half lo = __float2half_rn((v[k] - __half2float(hi)) * LOSCALE);
        int st = (c >> 7) * 12 + (d >> 4);
        int base = st * (2 * 128 * 24);
        int roff = (c & 127) * 24 + (d & 15);
        g_Bimg[base + roff]            = hi;
        g_Bimg[base + 128 * 24 + roff] = lo;
    }
    if (c0 == 0 && d == 0) { g_elatent = 0.f; g_bcount = 0; }

    __shared__ float sh[4][6];
#pragma unroll
    for (int k = 0; k < 4; k++) {
        float s = v[k] * v[k];
#pragma unroll
        for (int off = 16; off; off >>= 1) s += __shfl_down_sync(0xffffffffu, s, off);
        if ((d & 31) == 0) sh[k][d >> 5] = s;
    }
    __syncthreads();
    if (d < 4) {
        float t = 0.f;
#pragma unroll
        for (int j = 0; j < 6; j++) t += sh[d][j];
        g_cbnorm[c0 + d] = t;
    }
}

// ---------------------------------------------------------------------------
// K1 (fused): pool -> HMMA argmin (512 codes) -> scatter. 256 blocks x 256
// threads, 2 blocks/SM, single wave. Stage buffer recycling is protected by
// block-wide __syncthreads (no empty-mbarrier protocol).
// Phase C reconstructs fp32 pooled from the resident fp16 hi/lo smem.
// ---------------------------------------------------------------------------
__global__ void __launch_bounds__(256, 2) k_fused(const float* __restrict__ x,
                                                  const float* __restrict__ cb,
                                                  const float* __restrict__ w,
                                                  const float* __restrict__ bbias,
                                                  float* __restrict__ q,
                                                  float* __restrict__ idxo,
                                                  float* __restrict__ out_bnd) {
    extern __shared__ __align__(16) char sm[];
    __half* sAh    = (__half*)(sm + SM_AH);
    __half* sAl    = (__half*)(sm + SM_AL);
    char*   sB     = sm + SM_B;
    float*  sCN    = (float*)(sm + SM_CN);
    float*  sBP    = (float*)(sm + SM_BP);
    float*  sPN    = (float*)(sm + SM_PN);
    float*  sPNORM = (float*)(sm + SM_PNORM);
    float*  sBEST2 = (float*)(sm + SM_BEST2);
    int*    sIDX2  = (int*)(sm + SM_IDX2);
    float*  sBEST  = (float*)(sm + SM_BEST);
    int*    sIDX   = (int*)(sm + SM_IDX);
    __shared__ __align__(8) unsigned long long bar[2];   // full0, full1
    __shared__ int   sBC;
    __shared__ float sEL;

    int tid = threadIdx.x;
    int segbase = blockIdx.x * 64;

    unsigned full[2] = { smaddr(&bar[0]), smaddr(&bar[1]) };

    if (tid == 0) {
        mbar_init(full[0], 1);
        mbar_init(full[1], 1);
        sBC = 0; sEL = 0.f;
        asm volatile("fence.proxy.async.shared::cta;" ::: "memory");
    }
    __syncthreads();

    // kick off B stages 0,1 (overlaps phase A)
    if (tid == 0) {
#pragma unroll
        for (int st = 0; st < 2; st++) {
            mbar_expect(full[st], STG_B);
            bulk_g2s(smaddr(sB + st * STG_B), &g_Bimg[(size_t)st * (2 * 128 * 24)], STG_B, full[st]);
        }
    }
    // cbnorm into smem
#pragma unroll
    for (int k = 0; k < 2; k++) sCN[tid + k * 256] = __ldg(&g_cbnorm[tid + k * 256]);

    // ================= Phase A: pooling + boundary + fp16 splits =================
    {
        int s    = tid >> 2;      // 0..63 local seg
        int part = tid & 3;
        const float4* xr  = (const float4*)x + (size_t)(segbase + s) * 384;
        const float4* w4p = (const float4*)w;

        float bpart[SPAN];
#pragma unroll
        for (int j = 0; j < SPAN; j++) bpart[j] = 0.f;
        float pnp = 0.f;

#pragma unroll 3
        for (int i = 0; i < 12; i++) {
            int d4 = i * 4 + part;
            float4 w4 = w4p[d4];
            float4 ps = make_float4(0.f, 0.f, 0.f, 0.f);
#pragma unroll
            for (int j = 0; j < SPAN; j++) {
                float4 v = xr[j * 48 + d4];
                ps.x += v.x; ps.y += v.y; ps.z += v.z; ps.w += v.w;
                bpart[j] += v.x * w4.x + v.y * w4.y + v.z * w4.z + v.w * w4.w;
            }
            ps.x *= 0.125f; ps.y *= 0.125f; ps.z *= 0.125f; ps.w *= 0.125f;

            // fp16 hi/lo splits into A smem [m][200] layout
            __half hx = __float2half_rn(ps.x), hy = __float2half_rn(ps.y);
            __half hz = __float2half_rn(ps.z), hw = __float2half_rn(ps.w);
            int hb = s * 200 + d4 * 4;
            *(__half2*)(sAh + hb)     = __halves2half2(hx, hy);
            *(__half2*)(sAh + hb + 2) = __halves2half2(hz, hw);
            *(__half2*)(sAl + hb) = __halves2half2(
                __float2half_rn((ps.x - __half2float(hx)) * LOSCALE),
                __float2half_rn((ps.y - __half2float(hy)) * LOSCALE));
            *(__half2*)(sAl + hb + 2) = __halves2half2(
                __float2half_rn((ps.z - __half2float(hz)) * LOSCALE),
                __float2half_rn((ps.w - __half2float(hw)) * LOSCALE));

            pnp += ps.x * ps.x + ps.y * ps.y + ps.z * ps.z + ps.w * ps.w;
        }
#pragma unroll
        for (int j = 0; j < SPAN; j++) sBP[s * 32 + part * 8 + j] = bpart[j];
        sPN[s * 4 + part] = pnp;
    }
    __syncthreads();

    // boundary logits + count; pnorm fold
    {
        float bias = __ldg(bbias);
        unsigned cnt = 0;
#pragma unroll
        for (int k = 0; k < 2; k++) {
            int t2 = tid + k * 256;            // 0..511 = seg*8 + j
            int s2 = t2 >> 3, j2 = t2 & 7;
            float z = bias + sBP[s2 * 32 + j2] + sBP[s2 * 32 + 8 + j2]
                           + sBP[s2 * 32 + 16 + j2] + sBP[s2 * 32 + 24 + j2];
            bool hi = z > 0.f;
            out_bnd[(size_t)(segbase + s2) * 8 + j2] = hi ? 1.f : 0.f;
            cnt += hi ? 1u : 0u;
        }
        unsigned wsum = __reduce_add_sync(0xffffffffu, cnt);
        if ((tid & 31) == 0) atomicAdd(&sBC, (int)wsum);
        if (tid < 64)
            sPNORM[tid] = sPN[tid * 4] + sPN[tid * 4 + 1] + sPN[tid * 4 + 2] + sPN[tid * 4 + 3];
    }
    __syncthreads();

    // ================= Phase B: HMMA argmin over 512 codes =================
    int wid  = tid >> 5;
    int lane = tid & 31;
    int wm   = wid & 3;        // m16 tile (segs wm*16..+15)
    int nh   = wid >> 2;       // n64 half of each 128-code stage

    // ldmatrix lane address offsets
    int a_moff = (lane & 7) + ((lane >> 3) & 1) * 8;
    int a_koff = (lane >> 4) * 8;
    unsigned aRow = (unsigned)((wm * 16 + a_moff) * 200 + a_koff);  // halves
    unsigned aHaddr = smaddr(sAh) + aRow * 2;
    unsigned aLaddr = smaddr(sAl) + aRow * 2;

    int b_noff = (lane & 7) + ((lane >> 4) << 3);
    int b_koff = ((lane >> 3) & 1) * 8;
    unsigned bOff = (unsigned)((nh * 64 + b_noff) * 48 + b_koff * 2);  // bytes within split

    int rowA = lane >> 2;          // 0..7 -> m rows wm*16+rowA, +8
    int colP = (lane & 3) * 2;     // code pair base within n8 tile

    float bestA = 3.4e38f, bestB = 3.4e38f;
    int   idxA = 0, idxB = 0;

    int st = 0;
    for (int nt = 0; nt < 4; nt++) {
        float dhi[8][4], dlo[8][4];
#pragma unroll
        for (int t = 0; t < 8; t++)
#pragma unroll
            for (int r = 0; r < 4; r++) { dhi[t][r] = 0.f; dlo[t][r] = 0.f; }

        for (int ch = 0; ch < 12; ch++, st++) {
            int buf = st & 1;
            unsigned par = (st >> 1) & 1;
            mbar_wait(full[buf], par);

            uint32_t ah[4], al[4];
            unsigned ka = (unsigned)(ch * 16) * 2;
            ldsm4(ah[0], ah[1], ah[2], ah[3], aHaddr + ka);
            ldsm4(al[0], al[1], al[2], al[3], aLaddr + ka);

            unsigned bh_base = smaddr(sB + buf * STG_B) + bOff;
            unsigned bl_base = bh_base + SPLIT_B;

#pragma unroll
            for (int t2 = 0; t2 < 4; t2++) {
                uint32_t bh0, bh1, bh2, bh3, bl0, bl1, bl2, bl3;
                ldsm4(bh0, bh1, bh2, bh3, bh_base + t2 * (16 * 48));
                ldsm4(bl0, bl1, bl2, bl3, bl_base + t2 * (16 * 48));
                int t = t2 * 2;
                mma16816(dhi[t],     ah, bh0, bh1);
                mma16816(dlo[t],     ah, bl0, bl1);
                mma16816(dlo[t],     al, bh0, bh1);
                mma16816(dhi[t + 1], ah, bh2, bh3);
                mma16816(dlo[t + 1], ah, bl2, bl3);
                mma16816(dlo[t + 1], al, bh2, bh3);
            }

            // Block-wide barrier: every thread's reads of buf are complete
            // (register-consumed by the MMAs above) before anyone overwrites it.
            __syncthreads();
            if (tid == 0 && st + 2 < NSTAGE) {
                mbar_expect(full[buf], STG_B);
                bulk_g2s(smaddr(sB + buf * STG_B),
                         &g_Bimg[(size_t)(st + 2) * (2 * 128 * 24)], STG_B, full[buf]);
            }
        }

        // fold: val = ||c||^2 - 2*(dhi + dlo/2048)
#pragma unroll
        for (int t = 0; t < 8; t++) {
            int c0 = nt * 128 + nh * 64 + t * 8 + colP;
            float cn0 = sCN[c0], cn1 = sCN[c0 + 1];
            float v00 = cn0 - 2.f * (dhi[t][0] + dlo[t][0] * INVLO);  // row A, c0
            float v01 = cn1 - 2.f * (dhi[t][1] + dlo[t][1] * INVLO);  // row A, c0+1
            float v10 = cn0 - 2.f * (dhi[t][2] + dlo[t][2] * INVLO);  // row B, c0
            float v11 = cn1 - 2.f * (dhi[t][3] + dlo[t][3] * INVLO);  // row B, c0+1
            if (v00 < bestA || (v00 == bestA && c0 < idxA)) { bestA = v00; idxA = c0; }
            if (v01 < bestA || (v01 == bestA && (c0 + 1) < idxA)) { bestA = v01; idxA = c0 + 1; }
            if (v10 < bestB || (v10 == bestB && c0 < idxB)) { bestB = v10; idxB = c0; }
            if (v11 < bestB || (v11 == bestB && (c0 + 1) < idxB)) { bestB = v11; idxB = c0 + 1; }
        }
    }

    // reduce across the 4 lanes sharing each row (xor 1,2 within quad)
#pragma unroll
    for (int off = 1; off < 4; off <<= 1) {
        float ov = __shfl_xor_sync(0xffffffffu, bestA, off);
        int   oi = __shfl_xor_sync(0xffffffffu, idxA, off);
        if (ov < bestA || (ov == bestA && oi < idxA)) { bestA = ov; idxA = oi; }
        ov = __shfl_xor_sync(0xffffffffu, bestB, off);
        oi = __shfl_xor_sync(0xffffffffu, idxB, off);
        if (ov < bestB || (ov == bestB && oi < idxB)) { bestB = ov; idxB = oi; }
    }
    if ((lane & 3) == 0) {
        int mA = wm * 16 + rowA;
        sBEST2[mA * 2 + nh] = bestA;  sIDX2[mA * 2 + nh] = idxA;
        sBEST2[(mA + 8) * 2 + nh] = bestB;  sIDX2[(mA + 8) * 2 + nh] = idxB;
    }
    __syncthreads();

    // combine the two n-halves per segment
    if (tid < 64) {
        float b0 = sBEST2[tid * 2],     b1 = sBEST2[tid * 2 + 1];
        int   i0 = sIDX2[tid * 2],      i1 = sIDX2[tid * 2 + 1];
        bool take1 = (b1 < b0) || (b1 == b0 && i1 < i0);
        float bb = take1 ? b1 : b0;
        int   ii = take1 ? i1 : i0;
        sBEST[tid] = bb;  sIDX[tid] = ii;
        float v = sPNORM[tid] + bb;
#pragma unroll
        for (int off = 16; off; off >>= 1) v += __shfl_down_sync(0xffffffffu, v, off);
        if ((tid & 31) == 0) atomicAdd(&sEL, v);
    }
    __syncthreads();
    if (tid == 0) {
        atomicAdd(&g_elatent, sEL);
        atomicAdd(&g_bcount, sBC);
    }

    // ================= Phase C: scatter q_out + idx_out =================
    // pooled fp32 reconstructed from fp16 hi/lo: p' = hi + lo/2048
#pragma unroll 2
    for (int i = 0; i < 12; i++) {
        int task = tid + i * 256;            // 0..3071 = seg*48 + d4
        int s  = task / 48;
        int d4 = task - s * 48;
        int idx = sIDX[s];
        float4 c4 = __ldg((const float4*)(cb + (size_t)idx * DD) + d4);
        int hb = s * 200 + d4 * 4;
        __half2 h01 = *(__half2*)(sAh + hb);
        __half2 h23 = *(__half2*)(sAh + hb + 2);
        __half2 l01 = *(__half2*)(sAl + hb);
        __half2 l23 = *(__half2*)(sAl + hb + 2);
        float px = __half2float(__low2half(h01))  + __half2float(__low2half(l01))  * INVLO;
        float py = __half2float(__high2half(h01)) + __half2float(__high2half(l01)) * INVLO;
        float pz = __half2float(__low2half(h23))  + __half2float(__low2half(l23))  * INVLO;
        float pw = __half2float(__high2half(h23)) + __half2float(__high2half(l23)) * INVLO;
        float4 o;
        o.x = px + (c4.x - px);
        o.y = py + (c4.y - py);
        o.z = pz + (c4.z - pz);
        o.w = pw + (c4.w - pw);
        float4* qp = (float4*)(q + (size_t)(segbase + s) * (SPAN * DD)) + d4;
#pragma unroll
        for (int j = 0; j < SPAN; j++) qp[j * 48] = o;
    }
    if (tid < 64) {
        float v = (float)sIDX[tid];
        float* ip = idxo + (size_t)(segbase + tid) * SPAN;
#pragma unroll
        for (int j = 0; j < SPAN; j++) ip[j] = v;
    }
}

// ---------------------------------------------------------------------------
// K2: finalize scalar loss
// ---------------------------------------------------------------------------
__global__ void k_final(float* __restrict__ loss_out) {
    float e  = g_elatent * (1.0f / ((float)NSEG * (float)DD));
    float br = (float)g_bcount * (1.0f / (float)NTOK);
    float bl = br - (1.0f / SPAN);
    loss_out[0] = 0.25f * e + 0.01f * bl * bl;
}

// ---------------------------------------------------------------------------
extern "C" void kernel_launch(void* const* d_in, const int* in_sizes, int n_in,
                              void* d_out, int out_size) {
    const float* x  = (const float*)d_in[0];
    const float* cb = (const float*)d_in[1];
    const float* w  = (const float*)d_in[2];
    const float* bb = (const float*)d_in[3];
    float* out  = (float*)d_out;
    float* q    = out;
    float* loss = out + OFF_LOSS;
    float* idxo = out + OFF_IDX;
    float* bnd  = out + OFF_BND;

    cudaFuncSetAttribute(k_fused, cudaFuncAttributeMaxDynamicSharedMemorySize, SM_TOTAL);

    k_prep<<<KC / 4, DD>>>(cb);
    k_fused<<<NSEG / 64, 256, SM_TOTAL>>>(x, cb, w, bb, q, idxo, bnd);
    k_final<<<1, 1>>>(loss);
}